// round 8
// baseline (speedup 1.0000x reference)
#include <cuda_runtime.h>
#include <cuda_bf16.h>
#include <cstdint>
#include <math.h>

// Problem constants
#define LL 1024
#define BB 2
#define FF 1024
#define HH 2048
#define NN 16
#define RR 64
#define KK 4
#define MROWS (LL*BB)        // 2048
#define PROJC (RR + 2*NN)    // 96

typedef __nv_bfloat16 bf16;

// ---------------- scratch (device globals: allocation-free) ----------------
// split-bf16 operands
__device__ bf16 g_xh [(size_t)MROWS * FF],      g_xl [(size_t)MROWS * FF];
__device__ bf16 g_Winh[(size_t)(2*HH) * FF],    g_Winl[(size_t)(2*HH) * FF];
__device__ bf16 g_xsh[(size_t)MROWS * HH],      g_xsl[(size_t)MROWS * HH];
__device__ bf16 g_Wch[(size_t)HH * (KK*1024)],  g_Wcl[(size_t)HH * (KK*1024)];
__device__ bf16 g_uh [(size_t)MROWS * HH],      g_ul [(size_t)MROWS * HH];
__device__ bf16 g_Wsh[(size_t)128 * HH],        g_Wsl[(size_t)128 * HH];
__device__ bf16 g_dth[(size_t)MROWS * RR],      g_dtl[(size_t)MROWS * RR];
__device__ bf16 g_Wdh[(size_t)HH * RR],         g_Wdl[(size_t)HH * RR];
__device__ bf16 g_zh [(size_t)MROWS * HH],      g_zl [(size_t)MROWS * HH];
__device__ bf16 g_Woh[(size_t)FF * HH],         g_Wol[(size_t)FF * HH];
// fp32 intermediates for the scan
__device__ float g_res  [(size_t)MROWS * HH];
__device__ float g_u    [(size_t)MROWS * HH];
__device__ float g_proj [(size_t)MROWS * PROJC];
__device__ float g_delta[(size_t)MROWS * HH];

// ---------------- tiling ----------------------------------------------------
#define BM 128
#define BN 128
#define BK 32
#define ROW_B   80                       // bytes per smem row (32 bf16 + pad)
#define ARR_B   (128 * ROW_B)            // 10240 B per operand tile
#define STAGE_B (4 * ARR_B)              // Ah,Al,Bh,Bl = 40960 B
#define SMEM_TOTAL (2 * STAGE_B)         // 81920 B

__device__ __forceinline__ float sigmoid_f(float x) {
    return 1.f / (1.f + __expf(-x));
}
__device__ __forceinline__ void fsplit(float v, bf16* hp, bf16* lp) {
    bf16 h = __float2bfloat16(v);
    *hp = h;
    *lp = __float2bfloat16(v - __bfloat162float(h));
}
__device__ __forceinline__ void mma_bf16(float* d, const unsigned* a, const unsigned* b) {
    asm volatile(
        "mma.sync.aligned.m16n8k16.row.col.f32.bf16.bf16.f32 "
        "{%0,%1,%2,%3}, {%4,%5,%6,%7}, {%8,%9}, {%0,%1,%2,%3};\n"
        : "+f"(d[0]), "+f"(d[1]), "+f"(d[2]), "+f"(d[3])
        : "r"(a[0]), "r"(a[1]), "r"(a[2]), "r"(a[3]), "r"(b[0]), "r"(b[1]));
}
__device__ __forceinline__ void cp16(void* smem_dst, const void* gsrc, bool valid) {
    unsigned s = (unsigned)__cvta_generic_to_shared(smem_dst);
    int sz = valid ? 16 : 0;
    asm volatile("cp.async.cg.shared.global [%0], [%1], 16, %2;\n"
                 :: "r"(s), "l"(gsrc), "r"(sz));
}
#define CP_COMMIT() asm volatile("cp.async.commit_group;\n")
#define CP_WAIT0()  asm volatile("cp.async.wait_group 0;\n")

// ---------------- pre-passes -------------------------------------------------
__global__ void split_k(const float* __restrict__ in, bf16* __restrict__ oh,
                        bf16* __restrict__ ol, int n)
{
    int i = blockIdx.x * blockDim.x + threadIdx.x;
    if (i < n) fsplit(in[i], &oh[i], &ol[i]);
}

// in [Kd][Nd] fp32 -> outh/outl [Npad][Kd] split-bf16 (rows >= Nd zero)
__global__ void trsplit_k(const float* __restrict__ in, bf16* __restrict__ oh,
                          bf16* __restrict__ ol, int Kd, int Nd, int Npad)
{
    __shared__ float tile[32][33];
    int k0 = blockIdx.x * 32, n0 = blockIdx.y * 32;
    for (int i = threadIdx.y; i < 32; i += 8) {
        int k = k0 + i, n = n0 + threadIdx.x;
        tile[i][threadIdx.x] = (k < Kd && n < Nd) ? in[(size_t)k * Nd + n] : 0.f;
    }
    __syncthreads();
    for (int i = threadIdx.y; i < 32; i += 8) {
        int n = n0 + i, k = k0 + threadIdx.x;
        if (n < Npad && k < Kd)
            fsplit(tile[threadIdx.x][i], &oh[(size_t)n * Kd + k], &ol[(size_t)n * Kd + k]);
    }
}

// ============ split-bf16 tensor GEMM: 128x128xK, 256 thr, 8 warps ==========
// C = (Ah+Al)[M,K] @ (Bh+Bl)[N,K]^T  via  Ah*Bh + Ah*Bl + Al*Bh
// EPI 0: GEMM1  (c<HH -> split to Coh/Col; else Cf = res)
// EPI 1: conv   (silu(v+bias) -> Cf fp32 + split Coh/Col)
// EPI 2: proj   (c<96 -> Cf[ldc=96]; 32<=c<96 -> split dt at col c-32)
// EPI 3: delta  (softplus(v+bias) -> Cf)
// EPI 4: out    (Cf plain)
template<int EPI, int CONV>
__global__ __launch_bounds__(256, 2)
void tc_gemm(const bf16* __restrict__ Ah, const bf16* __restrict__ Al, int lda,
             const bf16* __restrict__ Bh, const bf16* __restrict__ Bl, int ldb,
             float* __restrict__ Cf, bf16* __restrict__ Coh, bf16* __restrict__ Col,
             int Nn, int Kk, const float* __restrict__ bias)
{
    extern __shared__ __align__(16) char smem[];

    const int tid  = threadIdx.x;
    const int col0 = blockIdx.x * BN;
    const int row0 = blockIdx.y * BM;
    const int grp  = CONV ? (col0 >> 10) : 0;
    const int warp = tid >> 5;
    const int lane = tid & 31;
    const int gid  = lane >> 2;        // 0..7
    const int tig  = lane & 3;         // 0..3
    const int wm0  = (warp & 3) * 32;
    const int wn0  = (warp >> 2) * 64;

    auto ld_tile = [&](int kt, int stage) {
        char* base = smem + stage * STAGE_B;
        // each operand: 128 rows x 32 bf16 = 512 x 16B chunks, 2 per thread
#pragma unroll
        for (int i = 0; i < 2; i++) {
            int q = tid + i * 256;
            int m = q >> 2, j = (q & 3) * 8;       // row, bf16 offset
            char* dst = base + m * ROW_B + j * 2;
            const bf16 *sh, *sl;
            bool valid = true;
            if (CONV) {
                int tap = kt >> 10, ci0 = kt & 1023, shift = 2 * (3 - tap);
                int rs = row0 + m - shift;
                valid = rs >= 0;
                size_t off = (size_t)(valid ? rs : 0) * lda + grp * 1024 + ci0 + j;
                sh = Ah + off; sl = Al + off;
            } else {
                size_t off = (size_t)(row0 + m) * lda + kt + j;
                sh = Ah + off; sl = Al + off;
            }
            cp16(dst, sh, valid);
            cp16(dst + ARR_B, sl, valid);
        }
#pragma unroll
        for (int i = 0; i < 2; i++) {
            int q = tid + i * 256;
            int n = q >> 2, j = (q & 3) * 8;
            char* dst = base + 2 * ARR_B + n * ROW_B + j * 2;
            size_t off = (size_t)(col0 + n) * ldb + kt + j;
            cp16(dst, Bh + off, true);
            cp16(dst + ARR_B, Bl + off, true);
        }
        CP_COMMIT();
    };

    float acc[2][8][4];
#pragma unroll
    for (int mt = 0; mt < 2; mt++)
#pragma unroll
        for (int nt = 0; nt < 8; nt++)
#pragma unroll
            for (int q = 0; q < 4; q++) acc[mt][nt][q] = 0.f;

    ld_tile(0, 0);
    CP_WAIT0();
    __syncthreads();

    const int T = Kk / BK;
    for (int t = 0; t < T; t++) {
        const int stage = t & 1;
        if (t + 1 < T) ld_tile((t + 1) * BK, stage ^ 1);

        const unsigned* A32h = (const unsigned*)(smem + stage * STAGE_B);
        const unsigned* A32l = (const unsigned*)(smem + stage * STAGE_B + ARR_B);
        const unsigned* B32h = (const unsigned*)(smem + stage * STAGE_B + 2 * ARR_B);
        const unsigned* B32l = (const unsigned*)(smem + stage * STAGE_B + 3 * ARR_B);
        const int RW = ROW_B / 4;   // 20 words per row

#pragma unroll
        for (int c = 0; c < 2; c++) {      // two k16 chunks
            unsigned ah[2][4], al[2][4], bh[8][2], bl[8][2];
#pragma unroll
            for (int mt = 0; mt < 2; mt++) {
                int r0 = (wm0 + mt * 16 + gid) * RW + c * 8;
                int r1 = r0 + 8 * RW;
                ah[mt][0] = A32h[r0 + tig];     ah[mt][1] = A32h[r1 + tig];
                ah[mt][2] = A32h[r0 + tig + 4]; ah[mt][3] = A32h[r1 + tig + 4];
                al[mt][0] = A32l[r0 + tig];     al[mt][1] = A32l[r1 + tig];
                al[mt][2] = A32l[r0 + tig + 4]; al[mt][3] = A32l[r1 + tig + 4];
            }
#pragma unroll
            for (int nt = 0; nt < 8; nt++) {
                int nb = (wn0 + nt * 8 + gid) * RW + c * 8;
                bh[nt][0] = B32h[nb + tig]; bh[nt][1] = B32h[nb + tig + 4];
                bl[nt][0] = B32l[nb + tig]; bl[nt][1] = B32l[nb + tig + 4];
            }
            // term-major: streams of independent MMAs
#pragma unroll
            for (int mt = 0; mt < 2; mt++)
#pragma unroll
                for (int nt = 0; nt < 8; nt++) mma_bf16(acc[mt][nt], ah[mt], bh[nt]);
#pragma unroll
            for (int mt = 0; mt < 2; mt++)
#pragma unroll
                for (int nt = 0; nt < 8; nt++) mma_bf16(acc[mt][nt], ah[mt], bl[nt]);
#pragma unroll
            for (int mt = 0; mt < 2; mt++)
#pragma unroll
                for (int nt = 0; nt < 8; nt++) mma_bf16(acc[mt][nt], al[mt], bh[nt]);
        }

        if (t + 1 < T) {
            CP_WAIT0();
            __syncthreads();
        }
    }

    auto epi_store = [&](int r, int c, float v) {
        if (EPI == 0) {
            if (c < HH) fsplit(v, &Coh[(size_t)r * HH + c], &Col[(size_t)r * HH + c]);
            else        Cf[(size_t)r * HH + (c - HH)] = v;
        } else if (EPI == 1) {
            v += bias[c]; v = v * sigmoid_f(v);
            Cf[(size_t)r * HH + c] = v;
            fsplit(v, &Coh[(size_t)r * HH + c], &Col[(size_t)r * HH + c]);
        } else if (EPI == 2) {
            if (c < PROJC) {
                Cf[(size_t)r * PROJC + c] = v;
                if (c >= 2 * NN)
                    fsplit(v, &Coh[(size_t)r * RR + (c - 2 * NN)],
                              &Col[(size_t)r * RR + (c - 2 * NN)]);
            }
        } else if (EPI == 3) {
            v += bias[c];
            v = (v > 20.f) ? v : log1pf(expf(v));
            Cf[(size_t)r * HH + c] = v;
        } else {
            Cf[(size_t)r * FF + c] = v;
        }
    };

#pragma unroll
    for (int mt = 0; mt < 2; mt++) {
        int r = row0 + wm0 + mt * 16 + gid;
#pragma unroll
        for (int nt = 0; nt < 8; nt++) {
            int c = col0 + wn0 + nt * 8 + tig * 2;
            epi_store(r,     c,     acc[mt][nt][0]);
            epi_store(r,     c + 1, acc[mt][nt][1]);
            epi_store(r + 8, c,     acc[mt][nt][2]);
            epi_store(r + 8, c + 1, acc[mt][nt][3]);
        }
    }
}

// ---------------- selective scan + fused z = y * silu(res) ----------------
__global__ __launch_bounds__(256)
void scan_k(const float* __restrict__ delta, const float* __restrict__ u,
            const float* __restrict__ proj, const float* __restrict__ A_log,
            const float* __restrict__ D, const float* __restrict__ res,
            bf16* __restrict__ zh, bf16* __restrict__ zl)
{
    const int gtid = blockIdx.x * blockDim.x + threadIdx.x;
    const int warp = gtid >> 5;
    const int lane = threadIdx.x & 31;
    const int sub  = lane >> 4;
    const int n    = lane & 15;
    const int c    = warp * 2 + sub;
    const int hi   = c >> 1;
    const int b    = c & 1;

    const float A  = -expf(A_log[hi * NN + n]);
    const float Dh = D[hi];
    float s = 0.f;

    for (int t = 0; t < LL; t++) {
        const int r = t * BB + b;
        float dt = __ldg(&delta[(size_t)r * HH + hi]);
        dt = fminf(fmaxf(dt, 0.001f), 0.1f);
        const float uu = __ldg(&u[(size_t)r * HH + hi]);
        const float Bn = __ldg(&proj[(size_t)r * PROJC + n]);
        const float Cn = __ldg(&proj[(size_t)r * PROJC + NN + n]);

        s = __expf(dt * A) * s + (dt * uu) * Bn;

        float p = Cn * s;
        p += __shfl_xor_sync(0xffffffffu, p, 1);
        p += __shfl_xor_sync(0xffffffffu, p, 2);
        p += __shfl_xor_sync(0xffffffffu, p, 4);
        p += __shfl_xor_sync(0xffffffffu, p, 8);

        if (n == 0) {
            const float yv = p + uu * Dh;
            const float rv = __ldg(&res[(size_t)r * HH + hi]);
            fsplit(yv * (rv * sigmoid_f(rv)),
                   &zh[(size_t)r * HH + hi], &zl[(size_t)r * HH + hi]);
        }
    }
}

// ---------------- launch ---------------------------------------------------
extern "C" void kernel_launch(void* const* d_in, const int* in_sizes, int n_in,
                              void* d_out, int out_size)
{
    const float* x      = (const float*)d_in[0];
    const float* W_in   = (const float*)d_in[1];
    const float* W_conv = (const float*)d_in[2];
    const float* b_conv = (const float*)d_in[3];
    const float* A_log  = (const float*)d_in[4];
    const float* D      = (const float*)d_in[5];
    const float* W_ssm  = (const float*)d_in[6];
    const float* W_dt   = (const float*)d_in[7];
    const float* b_dt   = (const float*)d_in[8];
    const float* W_out  = (const float*)d_in[9];
    float* out = (float*)d_out;

    void* p;
#define SYM(v, s) cudaGetSymbolAddress(&p, s); auto* v = decltype(&s[0])(p)
    SYM(xh, g_xh);   SYM(xl, g_xl);
    SYM(Winh, g_Winh); SYM(Winl, g_Winl);
    SYM(xsh, g_xsh); SYM(xsl, g_xsl);
    SYM(Wch, g_Wch); SYM(Wcl, g_Wcl);
    SYM(uh, g_uh);   SYM(ul, g_ul);
    SYM(Wsh, g_Wsh); SYM(Wsl, g_Wsl);
    SYM(dth, g_dth); SYM(dtl, g_dtl);
    SYM(Wdh, g_Wdh); SYM(Wdl, g_Wdl);
    SYM(zh, g_zh);   SYM(zl, g_zl);
    SYM(Woh, g_Woh); SYM(Wol, g_Wol);
    SYM(resb, g_res); SYM(ub, g_u); SYM(pb, g_proj); SYM(db, g_delta);
#undef SYM

    cudaFuncSetAttribute(tc_gemm<0,0>, cudaFuncAttributeMaxDynamicSharedMemorySize, SMEM_TOTAL);
    cudaFuncSetAttribute(tc_gemm<1,1>, cudaFuncAttributeMaxDynamicSharedMemorySize, SMEM_TOTAL);
    cudaFuncSetAttribute(tc_gemm<2,0>, cudaFuncAttributeMaxDynamicSharedMemorySize, SMEM_TOTAL);
    cudaFuncSetAttribute(tc_gemm<3,0>, cudaFuncAttributeMaxDynamicSharedMemorySize, SMEM_TOTAL);
    cudaFuncSetAttribute(tc_gemm<4,0>, cudaFuncAttributeMaxDynamicSharedMemorySize, SMEM_TOTAL);

    dim3 blk(256);
    dim3 tblk(32, 8);

    // 0) split input + transpose/split weights to [N][K]
    {
        int n = MROWS * FF;
        split_k<<<(n + 255) / 256, blk>>>(x, xh, xl, n);
    }
    trsplit_k<<<dim3(FF / 32, (2 * HH) / 32), tblk>>>(W_in, Winh, Winl, FF, 2 * HH, 2 * HH);
    trsplit_k<<<dim3((KK * 1024) / 32, HH / 32), tblk>>>(W_conv, Wch, Wcl, KK * 1024, HH, HH);
    trsplit_k<<<dim3(HH / 32, 128 / 32), tblk>>>(W_ssm, Wsh, Wsl, HH, PROJC, 128);
    trsplit_k<<<dim3(RR / 32, HH / 32), tblk>>>(W_dt, Wdh, Wdl, RR, HH, HH);
    trsplit_k<<<dim3(HH / 32, FF / 32), tblk>>>(W_out, Woh, Wol, HH, FF, FF);

    // 1) h = x @ W_in : xs half -> split(xsh/xsl), res half -> fp32 g_res
    tc_gemm<0, 0><<<dim3(2 * HH / BN, MROWS / BM), blk, SMEM_TOTAL>>>(
        xh, xl, FF, Winh, Winl, FF, resb, xsh, xsl, 2 * HH, FF, nullptr);

    // 2) u = silu(conv(xs) + b_conv) -> fp32 g_u + split(uh/ul)
    tc_gemm<1, 1><<<dim3(HH / BN, MROWS / BM), blk, SMEM_TOTAL>>>(
        xsh, xsl, HH, Wch, Wcl, KK * 1024, ub, uh, ul, HH, KK * 1024, b_conv);

    // 3) proj = u @ W_ssm -> fp32 g_proj; dt cols -> split(dth/dtl)
    tc_gemm<2, 0><<<dim3(1, MROWS / BM), blk, SMEM_TOTAL>>>(
        uh, ul, HH, Wsh, Wsl, HH, pb, dth, dtl, PROJC, HH, nullptr);

    // 4) delta = softplus(dt @ W_dt + b_dt) -> fp32 g_delta
    tc_gemm<3, 0><<<dim3(HH / BN, MROWS / BM), blk, SMEM_TOTAL>>>(
        dth, dtl, RR, Wdh, Wdl, RR, db, nullptr, nullptr, HH, RR, b_dt);

    // 5) selective scan + z = y * silu(res) -> split(zh/zl)
    scan_k<<<BB * HH * NN / 256, blk>>>(db, ub, pb, A_log, D, resb, zh, zl);

    // 6) out = z @ W_out -> fp32 out
    tc_gemm<4, 0><<<dim3(FF / BN, MROWS / BM), blk, SMEM_TOTAL>>>(
        zh, zl, HH, Woh, Wol, HH, out, nullptr, nullptr, FF, HH, nullptr);
}

// round 9
// speedup vs baseline: 1.4241x; 1.4241x over previous
#include <cuda_runtime.h>
#include <cuda_fp16.h>
#include <cstdint>
#include <math.h>

// Problem constants
#define LL 1024
#define BB 2
#define FF 1024
#define HH 2048
#define NN 16
#define RR 64
#define KK 4
#define MROWS (LL*BB)        // 2048
#define PROJC (RR + 2*NN)    // 96

typedef __half h16;

// ---------------- scratch (device globals: allocation-free) ----------------
__device__ h16 g_xh [(size_t)MROWS * FF];
__device__ h16 g_Win[(size_t)(2*HH) * FF];      // [4096][1024] K-major
__device__ h16 g_xs [(size_t)MROWS * HH];
__device__ h16 g_Wc [(size_t)HH * (KK*1024)];   // [2048][4096]
__device__ h16 g_uh [(size_t)MROWS * HH];
__device__ h16 g_Ws [(size_t)128 * HH];         // [128 pad][2048]
__device__ h16 g_dth[(size_t)MROWS * RR];
__device__ h16 g_Wd [(size_t)HH * RR];          // [2048][64]
__device__ h16 g_zh [(size_t)MROWS * HH];
__device__ h16 g_Wo [(size_t)FF * HH];          // [1024][2048]
// fp32 intermediates for the scan
__device__ float g_res  [(size_t)MROWS * HH];
__device__ float g_u    [(size_t)MROWS * HH];
__device__ float g_proj [(size_t)MROWS * PROJC];
__device__ float g_delta[(size_t)MROWS * HH];

// ---------------- tiling ----------------------------------------------------
#define BM 128
#define BN 128
#define BK 32
#define ROW_B   80                        // 32 halves (64B) + 16B pad
#define ARR_B   (128 * ROW_B)             // 10240 B per operand tile
#define STAGE_B (2 * ARR_B)               // A + B = 20480 B
#define NSTAGE  3
#define SMEM_TOTAL (NSTAGE * STAGE_B)     // 61440 B

__device__ __forceinline__ float sigmoid_f(float x) {
    return 1.f / (1.f + __expf(-x));
}
__device__ __forceinline__ void mma_f16(float* d, const unsigned* a, const unsigned* b) {
    asm volatile(
        "mma.sync.aligned.m16n8k16.row.col.f32.f16.f16.f32 "
        "{%0,%1,%2,%3}, {%4,%5,%6,%7}, {%8,%9}, {%0,%1,%2,%3};\n"
        : "+f"(d[0]), "+f"(d[1]), "+f"(d[2]), "+f"(d[3])
        : "r"(a[0]), "r"(a[1]), "r"(a[2]), "r"(a[3]), "r"(b[0]), "r"(b[1]));
}
__device__ __forceinline__ void ldm_x4(unsigned* r, unsigned saddr) {
    asm volatile("ldmatrix.sync.aligned.m8n8.x4.shared.b16 {%0,%1,%2,%3}, [%4];"
        : "=r"(r[0]), "=r"(r[1]), "=r"(r[2]), "=r"(r[3]) : "r"(saddr));
}
__device__ __forceinline__ void cp16(void* smem_dst, const void* gsrc, bool valid) {
    unsigned s = (unsigned)__cvta_generic_to_shared(smem_dst);
    int sz = valid ? 16 : 0;
    asm volatile("cp.async.cg.shared.global [%0], [%1], 16, %2;\n"
                 :: "r"(s), "l"(gsrc), "r"(sz));
}
#define CP_COMMIT() asm volatile("cp.async.commit_group;\n")
#define CP_WAIT(n)  asm volatile("cp.async.wait_group %0;\n" :: "n"(n))

// ---------------- pre-passes -------------------------------------------------
__global__ void tohalf_k(const float* __restrict__ in, h16* __restrict__ o, int n)
{
    int i = blockIdx.x * blockDim.x + threadIdx.x;
    if (i < n) o[i] = __float2half_rn(in[i]);
}

// in [Kd][Nd] fp32 -> out [Npad][Kd] fp16 (rows >= Nd zero)
__global__ void trhalf_k(const float* __restrict__ in, h16* __restrict__ o,
                         int Kd, int Nd, int Npad)
{
    __shared__ float tile[32][33];
    int k0 = blockIdx.x * 32, n0 = blockIdx.y * 32;
    for (int i = threadIdx.y; i < 32; i += 8) {
        int k = k0 + i, n = n0 + threadIdx.x;
        tile[i][threadIdx.x] = (k < Kd && n < Nd) ? in[(size_t)k * Nd + n] : 0.f;
    }
    __syncthreads();
    for (int i = threadIdx.y; i < 32; i += 8) {
        int n = n0 + i, k = k0 + threadIdx.x;
        if (n < Npad && k < Kd)
            o[(size_t)n * Kd + k] = __float2half_rn(tile[threadIdx.x][i]);
    }
}

// ============ fp16 tensor GEMM: 128x128xK, 256 thr, 8 warps ================
// C = A[M,K] @ B[N,K]^T, fp32 accum.
// EPI 0: GEMM1  (c<HH -> fp16 Ch; else Cf = res fp32)
// EPI 1: conv   (silu(v+bias) -> Cf fp32 + fp16 Ch)
// EPI 2: proj   (c<96 -> Cf[96]; 32<=c<96 -> fp16 dt at col c-32)
// EPI 3: delta  (softplus(v+bias) -> Cf)
// EPI 4: out    (Cf plain)
template<int EPI, int CONV>
__global__ __launch_bounds__(256, 2)
void tc_gemm(const h16* __restrict__ A, int lda,
             const h16* __restrict__ B, int ldb,
             float* __restrict__ Cf, h16* __restrict__ Ch,
             int Nn, int Kk, const float* __restrict__ bias)
{
    extern __shared__ __align__(16) char smem[];
    const unsigned smb = (unsigned)__cvta_generic_to_shared(smem);

    const int tid  = threadIdx.x;
    const int col0 = blockIdx.x * BN;
    const int row0 = blockIdx.y * BM;
    const int grp  = CONV ? (col0 >> 10) : 0;
    const int warp = tid >> 5;
    const int lane = tid & 31;
    const int gid  = lane >> 2;        // 0..7
    const int tig  = lane & 3;         // 0..3
    const int wm0  = (warp & 3) * 32;
    const int wn0  = (warp >> 2) * 64;
    const int sel  = lane >> 3;        // 0..3 (ldmatrix quadrant)
    const int lr   = lane & 7;         // 0..7 (ldmatrix row)

    auto ld_tile = [&](int kt, int stage) {
        char* base = smem + stage * STAGE_B;
        // A: 128 rows x 32 halves = 512 x 16B, 2 per thread
#pragma unroll
        for (int i = 0; i < 2; i++) {
            int q = tid + i * 256;
            int m = q >> 2, j = (q & 3) * 8;       // row, half-offset
            char* dst = base + m * ROW_B + j * 2;
            const h16* src;
            bool valid = true;
            if (CONV) {
                int tap = kt >> 10, ci0 = kt & 1023, shift = 2 * (3 - tap);
                int rs = row0 + m - shift;
                valid = rs >= 0;
                src = A + (size_t)(valid ? rs : 0) * lda + grp * 1024 + ci0 + j;
            } else {
                src = A + (size_t)(row0 + m) * lda + kt + j;
            }
            cp16(dst, src, valid);
        }
        // B: 128 rows x 32 halves
#pragma unroll
        for (int i = 0; i < 2; i++) {
            int q = tid + i * 256;
            int n = q >> 2, j = (q & 3) * 8;
            cp16(base + ARR_B + n * ROW_B + j * 2,
                 B + (size_t)(col0 + n) * ldb + kt + j, true);
        }
        CP_COMMIT();
    };

    float acc[2][8][4];
#pragma unroll
    for (int mt = 0; mt < 2; mt++)
#pragma unroll
        for (int nt = 0; nt < 8; nt++)
#pragma unroll
            for (int q = 0; q < 4; q++) acc[mt][nt][q] = 0.f;

    const int T = Kk / BK;
    ld_tile(0, 0);
    if (T > 1) ld_tile(BK, 1);

    for (int t = 0; t < T; t++) {
        const int stage = t % NSTAGE;
        if (t + 1 < T) CP_WAIT(1); else CP_WAIT(0);
        __syncthreads();
        if (t + 2 < T) ld_tile((t + 2) * BK, (t + 2) % NSTAGE);

        const unsigned Abase = smb + stage * STAGE_B;
        const unsigned Bbase = Abase + ARR_B;

#pragma unroll
        for (int c = 0; c < 2; c++) {             // two k16 chunks
            unsigned a[2][4], b[8][2];
#pragma unroll
            for (int mt = 0; mt < 2; mt++) {
                int row  = wm0 + mt * 16 + ((sel & 1) << 3) + lr;
                int wcol = c * 8 + ((sel >> 1) << 2);
                ldm_x4(a[mt], Abase + row * ROW_B + wcol * 4);
            }
#pragma unroll
            for (int pr = 0; pr < 4; pr++) {      // pairs of n-tiles
                unsigned r4[4];
                int row  = wn0 + pr * 16 + ((sel >> 1) << 3) + lr;
                int wcol = c * 8 + ((sel & 1) << 2);
                ldm_x4(r4, Bbase + row * ROW_B + wcol * 4);
                b[pr * 2][0]     = r4[0]; b[pr * 2][1]     = r4[1];
                b[pr * 2 + 1][0] = r4[2]; b[pr * 2 + 1][1] = r4[3];
            }
#pragma unroll
            for (int mt = 0; mt < 2; mt++)
#pragma unroll
                for (int nt = 0; nt < 8; nt++)
                    mma_f16(acc[mt][nt], a[mt], b[nt]);
        }
        __syncthreads();
    }

    auto epi_store = [&](int r, int c, float v) {
        if (EPI == 0) {
            if (c < HH) Ch[(size_t)r * HH + c] = __float2half_rn(v);
            else        Cf[(size_t)r * HH + (c - HH)] = v;
        } else if (EPI == 1) {
            v += bias[c]; v = v * sigmoid_f(v);
            Cf[(size_t)r * HH + c] = v;
            Ch[(size_t)r * HH + c] = __float2half_rn(v);
        } else if (EPI == 2) {
            if (c < PROJC) {
                Cf[(size_t)r * PROJC + c] = v;
                if (c >= 2 * NN)
                    Ch[(size_t)r * RR + (c - 2 * NN)] = __float2half_rn(v);
            }
        } else if (EPI == 3) {
            v += bias[c];
            v = (v > 20.f) ? v : log1pf(expf(v));
            Cf[(size_t)r * HH + c] = v;
        } else {
            Cf[(size_t)r * FF + c] = v;
        }
    };

#pragma unroll
    for (int mt = 0; mt < 2; mt++) {
        int r = row0 + wm0 + mt * 16 + gid;
#pragma unroll
        for (int nt = 0; nt < 8; nt++) {
            int c = col0 + wn0 + nt * 8 + tig * 2;
            epi_store(r,     c,     acc[mt][nt][0]);
            epi_store(r,     c + 1, acc[mt][nt][1]);
            epi_store(r + 8, c,     acc[mt][nt][2]);
            epi_store(r + 8, c + 1, acc[mt][nt][3]);
        }
    }
}

// ---------------- selective scan + fused z = y * silu(res) ----------------
__global__ __launch_bounds__(256)
void scan_k(const float* __restrict__ delta, const float* __restrict__ u,
            const float* __restrict__ proj, const float* __restrict__ A_log,
            const float* __restrict__ D, const float* __restrict__ res,
            h16* __restrict__ zh)
{
    const int gtid = blockIdx.x * blockDim.x + threadIdx.x;
    const int warp = gtid >> 5;
    const int lane = threadIdx.x & 31;
    const int sub  = lane >> 4;
    const int n    = lane & 15;
    const int c    = warp * 2 + sub;
    const int hi   = c >> 1;
    const int b    = c & 1;

    const float A  = -expf(A_log[hi * NN + n]);
    const float Dh = D[hi];
    float s = 0.f;

    for (int t = 0; t < LL; t++) {
        const int r = t * BB + b;
        float dt = __ldg(&delta[(size_t)r * HH + hi]);
        dt = fminf(fmaxf(dt, 0.001f), 0.1f);
        const float uu = __ldg(&u[(size_t)r * HH + hi]);
        const float Bn = __ldg(&proj[(size_t)r * PROJC + n]);
        const float Cn = __ldg(&proj[(size_t)r * PROJC + NN + n]);

        s = __expf(dt * A) * s + (dt * uu) * Bn;

        float p = Cn * s;
        p += __shfl_xor_sync(0xffffffffu, p, 1);
        p += __shfl_xor_sync(0xffffffffu, p, 2);
        p += __shfl_xor_sync(0xffffffffu, p, 4);
        p += __shfl_xor_sync(0xffffffffu, p, 8);

        if (n == 0) {
            const float yv = p + uu * Dh;
            const float rv = __ldg(&res[(size_t)r * HH + hi]);
            zh[(size_t)r * HH + hi] = __float2half_rn(yv * (rv * sigmoid_f(rv)));
        }
    }
}

// ---------------- launch ---------------------------------------------------
extern "C" void kernel_launch(void* const* d_in, const int* in_sizes, int n_in,
                              void* d_out, int out_size)
{
    const float* x      = (const float*)d_in[0];
    const float* W_in   = (const float*)d_in[1];
    const float* W_conv = (const float*)d_in[2];
    const float* b_conv = (const float*)d_in[3];
    const float* A_log  = (const float*)d_in[4];
    const float* D      = (const float*)d_in[5];
    const float* W_ssm  = (const float*)d_in[6];
    const float* W_dt   = (const float*)d_in[7];
    const float* b_dt   = (const float*)d_in[8];
    const float* W_out  = (const float*)d_in[9];
    float* out = (float*)d_out;

    void* p;
#define SYM(v, s) cudaGetSymbolAddress(&p, s); auto* v = decltype(&s[0])(p)
    SYM(xh, g_xh);   SYM(Win, g_Win);
    SYM(xs, g_xs);   SYM(Wc, g_Wc);
    SYM(uh, g_uh);   SYM(Ws, g_Ws);
    SYM(dth, g_dth); SYM(Wd, g_Wd);
    SYM(zh, g_zh);   SYM(Wo, g_Wo);
    SYM(resb, g_res); SYM(ub, g_u); SYM(pb, g_proj); SYM(db, g_delta);
#undef SYM

    cudaFuncSetAttribute(tc_gemm<0,0>, cudaFuncAttributeMaxDynamicSharedMemorySize, SMEM_TOTAL);
    cudaFuncSetAttribute(tc_gemm<1,1>, cudaFuncAttributeMaxDynamicSharedMemorySize, SMEM_TOTAL);
    cudaFuncSetAttribute(tc_gemm<2,0>, cudaFuncAttributeMaxDynamicSharedMemorySize, SMEM_TOTAL);
    cudaFuncSetAttribute(tc_gemm<3,0>, cudaFuncAttributeMaxDynamicSharedMemorySize, SMEM_TOTAL);
    cudaFuncSetAttribute(tc_gemm<4,0>, cudaFuncAttributeMaxDynamicSharedMemorySize, SMEM_TOTAL);

    dim3 blk(256);
    dim3 tblk(32, 8);

    // 0) fp16 conversions: x direct; weights transposed to [N][K]
    {
        int n = MROWS * FF;
        tohalf_k<<<(n + 255) / 256, blk>>>(x, xh, n);
    }
    trhalf_k<<<dim3(FF / 32, (2 * HH) / 32), tblk>>>(W_in, Win, FF, 2 * HH, 2 * HH);
    trhalf_k<<<dim3((KK * 1024) / 32, HH / 32), tblk>>>(W_conv, Wc, KK * 1024, HH, HH);
    trhalf_k<<<dim3(HH / 32, 128 / 32), tblk>>>(W_ssm, Ws, HH, PROJC, 128);
    trhalf_k<<<dim3(RR / 32, HH / 32), tblk>>>(W_dt, Wd, RR, HH, HH);
    trhalf_k<<<dim3(HH / 32, FF / 32), tblk>>>(W_out, Wo, HH, FF, FF);

    // 1) h = x @ W_in : xs half -> fp16 g_xs, res half -> fp32 g_res
    tc_gemm<0, 0><<<dim3(2 * HH / BN, MROWS / BM), blk, SMEM_TOTAL>>>(
        xh, FF, Win, FF, resb, xs, 2 * HH, FF, nullptr);

    // 2) u = silu(conv(xs) + b_conv) -> fp32 g_u + fp16 g_uh
    tc_gemm<1, 1><<<dim3(HH / BN, MROWS / BM), blk, SMEM_TOTAL>>>(
        xs, HH, Wc, KK * 1024, ub, uh, HH, KK * 1024, b_conv);

    // 3) proj = u @ W_ssm -> fp32 g_proj; dt cols -> fp16 g_dth
    tc_gemm<2, 0><<<dim3(1, MROWS / BM), blk, SMEM_TOTAL>>>(
        uh, HH, Ws, HH, pb, dth, PROJC, HH, nullptr);

    // 4) delta = softplus(dt @ W_dt + b_dt) -> fp32 g_delta
    tc_gemm<3, 0><<<dim3(HH / BN, MROWS / BM), blk, SMEM_TOTAL>>>(
        dth, RR, Wd, RR, db, nullptr, HH, RR, b_dt);

    // 5) selective scan + z = y * silu(res) -> fp16 g_zh
    scan_k<<<BB * HH * NN / 256, blk>>>(db, ub, pb, A_log, D, resb, zh);

    // 6) out = z @ W_out -> fp32 out
    tc_gemm<4, 0><<<dim3(FF / BN, MROWS / BM), blk, SMEM_TOTAL>>>(
        zh, HH, Wo, HH, out, nullptr, FF, HH, nullptr);
}